// round 10
// baseline (speedup 1.0000x reference)
#include <cuda_runtime.h>
#include <cuda_bf16.h>
#include <math.h>
#include <stdint.h>

#define E_ 8
#define D_ 1024
#define H_ 2048
#define T_ 2048

#define BM 128
#define BN 256
#define BK 16
#define NTHR 256    // 8 warps, 2x4 grid of 64x64 warp tiles

// SMEM stage geometry (floats)
#define A_STRIDE 20            // 16 + 4 pad -> conflict-free scalar A frag loads
#define B_STRIDE 264           // 256 + 8 pad -> conflict-free scalar B frag loads
#define A_FLOATS (BM * A_STRIDE)            // 2560
#define B_FLOATS (BK * B_STRIDE)            // 4224
#define STG_FLOATS (A_FLOATS + B_FLOATS)    // 6784
#define STG_BYTES (STG_FLOATS * 4)          // 27136
#define NSTAGE 4
#define SMEM_BYTES (NSTAGE * STG_BYTES)     // 108544

// ---------------------------------------------------------------------------
// Device scratch (allocation-free per harness rules)
// ---------------------------------------------------------------------------
__device__ float g_h[(size_t)E_ * T_ * H_];     // hidden acts (tf32-rounded fp32)
__device__ float g_Xr[(size_t)T_ * D_];         // X  tf32-rounded
__device__ float g_W1r[(size_t)E_ * D_ * H_];   // W1 tf32-rounded
__device__ float g_W2r[(size_t)E_ * H_ * D_];   // W2 tf32-rounded
__device__ int   g_cnt[E_];
__device__ int   g_tok[E_ * T_];
__device__ float g_wt[E_ * T_];

// ---------------------------------------------------------------------------
__device__ __forceinline__ uint32_t f2tf32(float v) {
    uint32_t r;
    asm("cvt.rna.tf32.f32 %0, %1;" : "=r"(r) : "f"(v));
    return r;
}

__device__ __forceinline__ void mma_tf32(float* c, const uint32_t* a, const uint32_t* b) {
    asm volatile(
        "mma.sync.aligned.m16n8k8.row.col.f32.tf32.tf32.f32 "
        "{%0,%1,%2,%3}, {%4,%5,%6,%7}, {%8,%9}, {%0,%1,%2,%3};"
        : "+f"(c[0]), "+f"(c[1]), "+f"(c[2]), "+f"(c[3])
        : "r"(a[0]), "r"(a[1]), "r"(a[2]), "r"(a[3]), "r"(b[0]), "r"(b[1]));
}

__device__ __forceinline__ uint32_t smem_u32(const void* p) {
    uint32_t a;
    asm("{ .reg .u64 t; cvta.to.shared.u64 t, %1; cvt.u32.u64 %0, t; }"
        : "=r"(a) : "l"(p));
    return a;
}

#define CP16(dst, src) \
    asm volatile("cp.async.cg.shared.global [%0], [%1], 16;" :: "r"(dst), "l"(src))
#define CP_COMMIT() asm volatile("cp.async.commit_group;")
#define CP_WAIT2()  asm volatile("cp.async.wait_group 2;")

__device__ __forceinline__ float gelu_tanh(float v) {
    float v3 = v * v * v;
    return 0.5f * v * (1.f + tanhf(0.7978845608028654f * (v + 0.044715f * v3)));
}

// ---------------------------------------------------------------------------
// Kernel: zero output + counters
// ---------------------------------------------------------------------------
__global__ void zero_kernel(float* __restrict__ out) {
    size_t i = (size_t)blockIdx.x * blockDim.x + threadIdx.x;
    ((float4*)out)[i] = make_float4(0.f, 0.f, 0.f, 0.f);
    if (blockIdx.x == 0 && threadIdx.x < E_) g_cnt[threadIdx.x] = 0;
}

// ---------------------------------------------------------------------------
// Kernel: tf32 round pre-pass (weights)
// ---------------------------------------------------------------------------
__global__ void rnd_kernel(const float* __restrict__ s, float* __restrict__ d) {
    size_t i = ((size_t)blockIdx.x * 256 + threadIdx.x) * 4;
    float4 v = *(const float4*)(s + i);
    uint4 o;
    o.x = f2tf32(v.x); o.y = f2tf32(v.y); o.z = f2tf32(v.z); o.w = f2tf32(v.w);
    *(uint4*)(d + i) = o;
}

// ---------------------------------------------------------------------------
// Kernel: gate + fused X round (block t streams X row t anyway)
// ---------------------------------------------------------------------------
__global__ __launch_bounds__(256) void gate_kernel(
    const float* __restrict__ x, const float* __restrict__ Wg,
    const float* __restrict__ bg, float* __restrict__ out)
{
    int t = blockIdx.x;
    const float* xr = x + (size_t)t * D_;
    float* xout = g_Xr + (size_t)t * D_;

    float acc[E_];
#pragma unroll
    for (int e = 0; e < E_; e++) acc[e] = 0.f;

    for (int d = threadIdx.x; d < D_; d += 256) {
        float xv = xr[d];
        xout[d] = __uint_as_float(f2tf32(xv));   // fused round
        const float4* wr = (const float4*)(Wg + (size_t)d * E_);
        float4 w0 = wr[0], w1 = wr[1];
        acc[0] += xv * w0.x; acc[1] += xv * w0.y;
        acc[2] += xv * w0.z; acc[3] += xv * w0.w;
        acc[4] += xv * w1.x; acc[5] += xv * w1.y;
        acc[6] += xv * w1.z; acc[7] += xv * w1.w;
    }
#pragma unroll
    for (int off = 16; off > 0; off >>= 1)
#pragma unroll
        for (int e = 0; e < E_; e++)
            acc[e] += __shfl_down_sync(0xffffffffu, acc[e], off);

    __shared__ float sm[8][E_];
    int warp = threadIdx.x >> 5, lane = threadIdx.x & 31;
    if (lane == 0)
#pragma unroll
        for (int e = 0; e < E_; e++) sm[warp][e] = acc[e];
    __syncthreads();

    if (threadIdx.x == 0) {
        float lg[E_];
#pragma unroll
        for (int e = 0; e < E_; e++) {
            float s = bg[e];
#pragma unroll
            for (int w = 0; w < 8; w++) s += sm[w][e];
            lg[e] = s;
        }
        int e0 = 0;
#pragma unroll
        for (int e = 1; e < E_; e++) if (lg[e] > lg[e0]) e0 = e;
        int e1 = -1;
#pragma unroll
        for (int e = 0; e < E_; e++)
            if (e != e0 && (e1 < 0 || lg[e] > lg[e1])) e1 = e;

        float ex = expf(lg[e1] - lg[e0]);
        float inv = 1.f / (1.f + ex);
        float w0 = inv, w1 = ex * inv;

        out[(size_t)T_ * D_ + 2 * t]     = (float)e0;
        out[(size_t)T_ * D_ + 2 * t + 1] = (float)e1;

        int p0 = atomicAdd(&g_cnt[e0], 1);
        g_tok[e0 * T_ + p0] = t;  g_wt[e0 * T_ + p0] = w0;
        int p1 = atomicAdd(&g_cnt[e1], 1);
        g_tok[e1 * T_ + p1] = t;  g_wt[e1 * T_ + p1] = w1;
    }
}

// ===========================================================================
// 4-stage cp.async tf32 GEMM mainloop (R8 core — scalar frag loads,
// conflict-free; crossbar-bytes bound). 128x256 tile, 8 warps @ 64x64.
// ===========================================================================
template <int NCH>
__device__ __forceinline__ void gemm_pipe(
    float* sm, uint32_t smb,
    const float* const* asrc,    // [2] per-seg A source ptrs (chunk 0)
    const float* const* bsrc,    // [4] per-seg B source ptrs (chunk 0)
    int bstride, float acc[4][8][4])
{
    const int tid = threadIdx.x;
    const int lane = tid & 31, wid = tid >> 5;
    const int wm = wid & 1, wn = wid >> 1;
    const int t4 = lane & 3, g8 = lane >> 2;

    uint32_t dA[2], dB[4];
#pragma unroll
    for (int j = 0; j < 2; j++) {
        int seg = tid + NTHR * j;
        dA[j] = (uint32_t)(((seg >> 2) * A_STRIDE + (seg & 3) * 4) * 4);
    }
#pragma unroll
    for (int j = 0; j < 4; j++) {
        int seg = tid + NTHR * j;
        dB[j] = (uint32_t)(A_FLOATS * 4 + ((seg >> 6) * B_STRIDE + (seg & 63) * 4) * 4);
    }

#pragma unroll
    for (int i = 0; i < 4; i++)
#pragma unroll
        for (int j = 0; j < 8; j++)
#pragma unroll
            for (int q = 0; q < 4; q++) acc[i][j][q] = 0.f;

#pragma unroll
    for (int s = 0; s < NSTAGE - 1; s++) {
        uint32_t base = smb + s * STG_BYTES;
        size_t bo = (size_t)s * BK * bstride;
#pragma unroll
        for (int j = 0; j < 2; j++) CP16(base + dA[j], asrc[j] + s * BK);
#pragma unroll
        for (int j = 0; j < 4; j++) CP16(base + dB[j], bsrc[j] + bo);
        CP_COMMIT();
    }

    for (int ch = 0; ch < NCH; ++ch) {
        CP_WAIT2();
        __syncthreads();

        const int s = ch & (NSTAGE - 1);
        const float* As = sm + s * STG_FLOATS;                 // [m][k] str 20
        const float* Bsm = sm + s * STG_FLOATS + A_FLOATS;     // [k][n] str 264

#pragma unroll
        for (int kh = 0; kh < 2; ++kh) {
            const int k0 = kh * 8;
            uint32_t af[4][4], bf[8][2];
#pragma unroll
            for (int mi = 0; mi < 4; mi++) {
                int rm = wm * 64 + mi * 16;
                const float* r0 = As + (rm + g8) * A_STRIDE + k0 + t4;
                const float* r1 = As + (rm + g8 + 8) * A_STRIDE + k0 + t4;
                af[mi][0] = __float_as_uint(r0[0]);
                af[mi][1] = __float_as_uint(r1[0]);
                af[mi][2] = __float_as_uint(r0[4]);
                af[mi][3] = __float_as_uint(r1[4]);
            }
#pragma unroll
            for (int ni = 0; ni < 8; ni++) {
                int cb = wn * 64 + ni * 8 + g8;
                bf[ni][0] = __float_as_uint(Bsm[(k0 + t4) * B_STRIDE + cb]);
                bf[ni][1] = __float_as_uint(Bsm[(k0 + t4 + 4) * B_STRIDE + cb]);
            }
#pragma unroll
            for (int mi = 0; mi < 4; mi++)
#pragma unroll
                for (int ni = 0; ni < 8; ni++)
                    mma_tf32(acc[mi][ni], af[mi], bf[ni]);
        }

        int nch = ch + NSTAGE - 1;
        if (nch < NCH) {
            uint32_t base = smb + (nch & (NSTAGE - 1)) * STG_BYTES;
            size_t bo = (size_t)nch * BK * bstride;
#pragma unroll
            for (int j = 0; j < 2; j++) CP16(base + dA[j], asrc[j] + nch * BK);
#pragma unroll
            for (int j = 0; j < 4; j++) CP16(base + dB[j], bsrc[j] + bo);
        }
        CP_COMMIT();
    }
}

// ---------------------------------------------------------------------------
// GEMM1 (per expert e): h[slot] = tf32round(gelu(Xr[tok] @ W1r[e] + b1[e]))
// ---------------------------------------------------------------------------
__global__ __launch_bounds__(NTHR, 1) void gemm1_mma(int e, const float* __restrict__ b1)
{
    int ne = g_cnt[e];
    int row0 = blockIdx.x * BM;
    if (row0 >= ne) return;
    int n0 = blockIdx.y * BN;

    extern __shared__ float sm[];
    uint32_t smb = smem_u32(sm);
    __shared__ int s_tok[BM];

    int tid = threadIdx.x;
    if (tid < BM) {
        int r = row0 + tid;
        s_tok[tid] = (r < ne) ? g_tok[e * T_ + r] : 0;
    }
    __syncthreads();

    const float* asrc[2];
    const float* bsrc[4];
    const float* wbase = g_W1r + (size_t)e * D_ * H_ + n0;
#pragma unroll
    for (int j = 0; j < 2; j++) {
        int seg = tid + NTHR * j;
        asrc[j] = g_Xr + (size_t)s_tok[seg >> 2] * D_ + (seg & 3) * 4;
    }
#pragma unroll
    for (int j = 0; j < 4; j++) {
        int seg = tid + NTHR * j;
        bsrc[j] = wbase + (size_t)(seg >> 6) * H_ + (seg & 63) * 4;
    }

    float acc[4][8][4];
    gemm_pipe<D_ / BK>(sm, smb, asrc, bsrc, H_, acc);

    const int lane = tid & 31, wid = tid >> 5;
    const int wm = wid & 1, wn = wid >> 1;
    const int t4 = lane & 3, g8 = lane >> 2;
    const float* bb = b1 + (size_t)e * H_ + n0;
#pragma unroll
    for (int mi = 0; mi < 4; mi++) {
        int rl0 = wm * 64 + mi * 16 + g8;
#pragma unroll
        for (int half = 0; half < 2; half++) {
            int r = row0 + rl0 + half * 8;
            if (r >= ne) continue;
            float* orow = g_h + ((size_t)(e * T_ + r)) * H_ + n0;
#pragma unroll
            for (int ni = 0; ni < 8; ni++) {
                int cn = wn * 64 + ni * 8 + t4 * 2;
                float v0 = acc[mi][ni][half * 2]     + bb[cn];
                float v1 = acc[mi][ni][half * 2 + 1] + bb[cn + 1];
                float2 o;
                o.x = __uint_as_float(f2tf32(gelu_tanh(v0)));
                o.y = __uint_as_float(f2tf32(gelu_tanh(v1)));
                *(float2*)(orow + cn) = o;
            }
        }
    }
}

// ---------------------------------------------------------------------------
// GEMM2 (per expert e): out[tok] += w * (h[slot] @ W2r[e] + b2[e])
// ---------------------------------------------------------------------------
__global__ __launch_bounds__(NTHR, 1) void gemm2_mma(int e, const float* __restrict__ b2,
                                                     float* __restrict__ out)
{
    int ne = g_cnt[e];
    int row0 = blockIdx.x * BM;
    if (row0 >= ne) return;
    int n0 = blockIdx.y * BN;

    extern __shared__ float sm[];
    uint32_t smb = smem_u32(sm);

    int tid = threadIdx.x;
    const float* asrc[2];
    const float* bsrc[4];
    const float* wbase = g_W2r + (size_t)e * H_ * D_ + n0;
#pragma unroll
    for (int j = 0; j < 2; j++) {
        int seg = tid + NTHR * j;
        // rows >= ne read stale-but-finite scratch; masked in epilogue
        asrc[j] = g_h + ((size_t)(e * T_ + row0 + (seg >> 2))) * H_ + (seg & 3) * 4;
    }
#pragma unroll
    for (int j = 0; j < 4; j++) {
        int seg = tid + NTHR * j;
        bsrc[j] = wbase + (size_t)(seg >> 6) * D_ + (seg & 63) * 4;
    }

    float acc[4][8][4];
    gemm_pipe<H_ / BK>(sm, smb, asrc, bsrc, D_, acc);

    const int lane = tid & 31, wid = tid >> 5;
    const int wm = wid & 1, wn = wid >> 1;
    const int t4 = lane & 3, g8 = lane >> 2;
    const float* bb = b2 + (size_t)e * D_ + n0;
#pragma unroll
    for (int mi = 0; mi < 4; mi++) {
        int rl0 = wm * 64 + mi * 16 + g8;
#pragma unroll
        for (int half = 0; half < 2; half++) {
            int r = row0 + rl0 + half * 8;
            if (r >= ne) continue;
            int tok = g_tok[e * T_ + r];
            float wgt = g_wt[e * T_ + r];
            float* orow = out + (size_t)tok * D_ + n0;
#pragma unroll
            for (int ni = 0; ni < 8; ni++) {
                int cn = wn * 64 + ni * 8 + t4 * 2;
                atomicAdd(orow + cn,     wgt * (acc[mi][ni][half * 2]     + bb[cn]));
                atomicAdd(orow + cn + 1, wgt * (acc[mi][ni][half * 2 + 1] + bb[cn + 1]));
            }
        }
    }
}

// ---------------------------------------------------------------------------
extern "C" void kernel_launch(void* const* d_in, const int* in_sizes, int n_in,
                              void* d_out, int out_size)
{
    const float* x  = (const float*)d_in[0];
    const float* Wg = (const float*)d_in[1];
    const float* bg = (const float*)d_in[2];
    const float* W1 = (const float*)d_in[3];
    const float* b1 = (const float*)d_in[4];
    const float* W2 = (const float*)d_in[5];
    const float* b2 = (const float*)d_in[6];
    float* out = (float*)d_out;

    static int inited = 0;
    static cudaStream_t sW, sB;
    static cudaEvent_t ev_root, ev_w1, ev_w2, ev_h[E_], ev_join;
    if (!inited) {
        cudaFuncSetAttribute(gemm1_mma, cudaFuncAttributeMaxDynamicSharedMemorySize, SMEM_BYTES);
        cudaFuncSetAttribute(gemm2_mma, cudaFuncAttributeMaxDynamicSharedMemorySize, SMEM_BYTES);
        cudaStreamCreateWithFlags(&sW, cudaStreamNonBlocking);
        cudaStreamCreateWithFlags(&sB, cudaStreamNonBlocking);
        cudaEventCreateWithFlags(&ev_root, cudaEventDisableTiming);
        cudaEventCreateWithFlags(&ev_w1,   cudaEventDisableTiming);
        cudaEventCreateWithFlags(&ev_w2,   cudaEventDisableTiming);
        for (int e = 0; e < E_; e++)
            cudaEventCreateWithFlags(&ev_h[e], cudaEventDisableTiming);
        cudaEventCreateWithFlags(&ev_join, cudaEventDisableTiming);
        inited = 1;
    }

    float* w1r; cudaGetSymbolAddress((void**)&w1r, g_W1r);
    float* w2r; cudaGetSymbolAddress((void**)&w2r, g_W2r);

    // Fork point for side streams
    cudaEventRecord(ev_root, 0);
    cudaStreamWaitEvent(sW, ev_root, 0);
    cudaStreamWaitEvent(sB, ev_root, 0);

    // Side stream: weight rounding (W1 first — needed earliest)
    rnd_kernel<<<(E_ * D_ * H_) / 1024, 256, 0, sW>>>(W1, w1r);
    cudaEventRecord(ev_w1, sW);
    rnd_kernel<<<(E_ * H_ * D_) / 1024, 256, 0, sW>>>(W2, w2r);
    cudaEventRecord(ev_w2, sW);

    // Main stream: zero + gate (routing + fused X round)
    zero_kernel<<<(T_ * D_) / (256 * 4), 256>>>(out);
    gate_kernel<<<T_, 256>>>(x, Wg, bg, out);

    // GEMM1 per expert, pipelined with GEMM2 on sB
    cudaStreamWaitEvent(0, ev_w1, 0);
    cudaStreamWaitEvent(sB, ev_w2, 0);
    for (int e = 0; e < E_; e++) {
        gemm1_mma<<<dim3(T_ / BM, H_ / BN), NTHR, SMEM_BYTES>>>(e, b1);
        cudaEventRecord(ev_h[e], 0);
        cudaStreamWaitEvent(sB, ev_h[e], 0);
        gemm2_mma<<<dim3(T_ / BM, D_ / BN), NTHR, SMEM_BYTES, sB>>>(e, b2, out);
    }

    // Join everything back to the capture stream
    cudaEventRecord(ev_join, sB);
    cudaStreamWaitEvent(0, ev_join, 0);
}

// round 12
// speedup vs baseline: 3.4160x; 3.4160x over previous
#include <cuda_runtime.h>
#include <cuda_bf16.h>
#include <math.h>
#include <stdint.h>

#define E_ 8
#define D_ 1024
#define H_ 2048
#define T_ 2048

#define BM 128
#define BN 256
#define BK 16
#define NTHR 256    // 8 warps, 2x4 grid of 64x64 warp tiles

// SMEM stage geometry (floats)
#define A_STRIDE 20            // 16 + 4 pad -> conflict-free scalar A frag loads
#define B_STRIDE 264           // 256 + 8 pad -> conflict-free scalar B frag loads
#define A_FLOATS (BM * A_STRIDE)            // 2560
#define B_FLOATS (BK * B_STRIDE)            // 4224
#define STG_FLOATS (A_FLOATS + B_FLOATS)    // 6784
#define STG_BYTES (STG_FLOATS * 4)          // 27136
#define NSTAGE 4
#define SMEM_BYTES (NSTAGE * STG_BYTES)     // 108544

// ---------------------------------------------------------------------------
// Device scratch (allocation-free per harness rules)
// ---------------------------------------------------------------------------
__device__ float g_h[(size_t)E_ * T_ * H_];     // hidden acts (tf32-rounded fp32)
__device__ float g_Xr[(size_t)T_ * D_];         // X  tf32-rounded
__device__ float g_W1r[(size_t)E_ * D_ * H_];   // W1 tf32-rounded
__device__ float g_W2r[(size_t)E_ * H_ * D_];   // W2 tf32-rounded
__device__ int   g_cnt[E_];
__device__ int   g_tok[E_ * T_];
__device__ float g_wt[E_ * T_];

// ---------------------------------------------------------------------------
__device__ __forceinline__ uint32_t f2tf32(float v) {
    uint32_t r;
    asm("cvt.rna.tf32.f32 %0, %1;" : "=r"(r) : "f"(v));
    return r;
}

__device__ __forceinline__ void mma_tf32(float* c, const uint32_t* a, const uint32_t* b) {
    asm volatile(
        "mma.sync.aligned.m16n8k8.row.col.f32.tf32.tf32.f32 "
        "{%0,%1,%2,%3}, {%4,%5,%6,%7}, {%8,%9}, {%0,%1,%2,%3};"
        : "+f"(c[0]), "+f"(c[1]), "+f"(c[2]), "+f"(c[3])
        : "r"(a[0]), "r"(a[1]), "r"(a[2]), "r"(a[3]), "r"(b[0]), "r"(b[1]));
}

__device__ __forceinline__ uint32_t smem_u32(const void* p) {
    uint32_t a;
    asm("{ .reg .u64 t; cvta.to.shared.u64 t, %1; cvt.u32.u64 %0, t; }"
        : "=r"(a) : "l"(p));
    return a;
}

#define CP16(dst, src) \
    asm volatile("cp.async.cg.shared.global [%0], [%1], 16;" :: "r"(dst), "l"(src))
#define CP_COMMIT() asm volatile("cp.async.commit_group;")
#define CP_WAIT2()  asm volatile("cp.async.wait_group 2;")

__device__ __forceinline__ float gelu_tanh(float v) {
    float v3 = v * v * v;
    return 0.5f * v * (1.f + tanhf(0.7978845608028654f * (v + 0.044715f * v3)));
}

// ---------------------------------------------------------------------------
// Kernel: zero output + counters
// ---------------------------------------------------------------------------
__global__ void zero_kernel(float* __restrict__ out) {
    size_t i = (size_t)blockIdx.x * blockDim.x + threadIdx.x;
    ((float4*)out)[i] = make_float4(0.f, 0.f, 0.f, 0.f);
    if (blockIdx.x == 0 && threadIdx.x < E_) g_cnt[threadIdx.x] = 0;
}

// ---------------------------------------------------------------------------
// Kernel: tf32 round pre-pass (weights)
// ---------------------------------------------------------------------------
__global__ void rnd_kernel(const float* __restrict__ s, float* __restrict__ d) {
    size_t i = ((size_t)blockIdx.x * 256 + threadIdx.x) * 4;
    float4 v = *(const float4*)(s + i);
    uint4 o;
    o.x = f2tf32(v.x); o.y = f2tf32(v.y); o.z = f2tf32(v.z); o.w = f2tf32(v.w);
    *(uint4*)(d + i) = o;
}

// ---------------------------------------------------------------------------
// Kernel: gate + fused X round (block t streams X row t anyway)
// ---------------------------------------------------------------------------
__global__ __launch_bounds__(256) void gate_kernel(
    const float* __restrict__ x, const float* __restrict__ Wg,
    const float* __restrict__ bg, float* __restrict__ out)
{
    int t = blockIdx.x;
    const float* xr = x + (size_t)t * D_;
    float* xout = g_Xr + (size_t)t * D_;

    float acc[E_];
#pragma unroll
    for (int e = 0; e < E_; e++) acc[e] = 0.f;

    for (int d = threadIdx.x; d < D_; d += 256) {
        float xv = xr[d];
        xout[d] = __uint_as_float(f2tf32(xv));   // fused round
        const float4* wr = (const float4*)(Wg + (size_t)d * E_);
        float4 w0 = wr[0], w1 = wr[1];
        acc[0] += xv * w0.x; acc[1] += xv * w0.y;
        acc[2] += xv * w0.z; acc[3] += xv * w0.w;
        acc[4] += xv * w1.x; acc[5] += xv * w1.y;
        acc[6] += xv * w1.z; acc[7] += xv * w1.w;
    }
#pragma unroll
    for (int off = 16; off > 0; off >>= 1)
#pragma unroll
        for (int e = 0; e < E_; e++)
            acc[e] += __shfl_down_sync(0xffffffffu, acc[e], off);

    __shared__ float sm[8][E_];
    int warp = threadIdx.x >> 5, lane = threadIdx.x & 31;
    if (lane == 0)
#pragma unroll
        for (int e = 0; e < E_; e++) sm[warp][e] = acc[e];
    __syncthreads();

    if (threadIdx.x == 0) {
        float lg[E_];
#pragma unroll
        for (int e = 0; e < E_; e++) {
            float s = bg[e];
#pragma unroll
            for (int w = 0; w < 8; w++) s += sm[w][e];
            lg[e] = s;
        }
        int e0 = 0;
#pragma unroll
        for (int e = 1; e < E_; e++) if (lg[e] > lg[e0]) e0 = e;
        int e1 = -1;
#pragma unroll
        for (int e = 0; e < E_; e++)
            if (e != e0 && (e1 < 0 || lg[e] > lg[e1])) e1 = e;

        float ex = expf(lg[e1] - lg[e0]);
        float inv = 1.f / (1.f + ex);
        float w0 = inv, w1 = ex * inv;

        out[(size_t)T_ * D_ + 2 * t]     = (float)e0;
        out[(size_t)T_ * D_ + 2 * t + 1] = (float)e1;

        int p0 = atomicAdd(&g_cnt[e0], 1);
        g_tok[e0 * T_ + p0] = t;  g_wt[e0 * T_ + p0] = w0;
        int p1 = atomicAdd(&g_cnt[e1], 1);
        g_tok[e1 * T_ + p1] = t;  g_wt[e1 * T_ + p1] = w1;
    }
}

// ===========================================================================
// 4-stage cp.async tf32 GEMM mainloop (R8 core — scalar frag loads,
// conflict-free; crossbar-bytes bound). 128x256 tile, 8 warps @ 64x64.
// ===========================================================================
template <int NCH>
__device__ __forceinline__ void gemm_pipe(
    float* sm, uint32_t smb,
    const float* const* asrc,    // [2] per-seg A source ptrs (chunk 0)
    const float* const* bsrc,    // [4] per-seg B source ptrs (chunk 0)
    int bstride, float acc[4][8][4])
{
    const int tid = threadIdx.x;
    const int lane = tid & 31, wid = tid >> 5;
    const int wm = wid & 1, wn = wid >> 1;
    const int t4 = lane & 3, g8 = lane >> 2;

    uint32_t dA[2], dB[4];
#pragma unroll
    for (int j = 0; j < 2; j++) {
        int seg = tid + NTHR * j;
        dA[j] = (uint32_t)(((seg >> 2) * A_STRIDE + (seg & 3) * 4) * 4);
    }
#pragma unroll
    for (int j = 0; j < 4; j++) {
        int seg = tid + NTHR * j;
        dB[j] = (uint32_t)(A_FLOATS * 4 + ((seg >> 6) * B_STRIDE + (seg & 63) * 4) * 4);
    }

#pragma unroll
    for (int i = 0; i < 4; i++)
#pragma unroll
        for (int j = 0; j < 8; j++)
#pragma unroll
            for (int q = 0; q < 4; q++) acc[i][j][q] = 0.f;

#pragma unroll
    for (int s = 0; s < NSTAGE - 1; s++) {
        uint32_t base = smb + s * STG_BYTES;
        size_t bo = (size_t)s * BK * bstride;
#pragma unroll
        for (int j = 0; j < 2; j++) CP16(base + dA[j], asrc[j] + s * BK);
#pragma unroll
        for (int j = 0; j < 4; j++) CP16(base + dB[j], bsrc[j] + bo);
        CP_COMMIT();
    }

    for (int ch = 0; ch < NCH; ++ch) {
        CP_WAIT2();
        __syncthreads();

        const int s = ch & (NSTAGE - 1);
        const float* As = sm + s * STG_FLOATS;                 // [m][k] str 20
        const float* Bsm = sm + s * STG_FLOATS + A_FLOATS;     // [k][n] str 264

#pragma unroll
        for (int kh = 0; kh < 2; ++kh) {
            const int k0 = kh * 8;
            uint32_t af[4][4], bf[8][2];
#pragma unroll
            for (int mi = 0; mi < 4; mi++) {
                int rm = wm * 64 + mi * 16;
                const float* r0 = As + (rm + g8) * A_STRIDE + k0 + t4;
                const float* r1 = As + (rm + g8 + 8) * A_STRIDE + k0 + t4;
                af[mi][0] = __float_as_uint(r0[0]);
                af[mi][1] = __float_as_uint(r1[0]);
                af[mi][2] = __float_as_uint(r0[4]);
                af[mi][3] = __float_as_uint(r1[4]);
            }
#pragma unroll
            for (int ni = 0; ni < 8; ni++) {
                int cb = wn * 64 + ni * 8 + g8;
                bf[ni][0] = __float_as_uint(Bsm[(k0 + t4) * B_STRIDE + cb]);
                bf[ni][1] = __float_as_uint(Bsm[(k0 + t4 + 4) * B_STRIDE + cb]);
            }
#pragma unroll
            for (int mi = 0; mi < 4; mi++)
#pragma unroll
                for (int ni = 0; ni < 8; ni++)
                    mma_tf32(acc[mi][ni], af[mi], bf[ni]);
        }

        int nch = ch + NSTAGE - 1;
        if (nch < NCH) {
            uint32_t base = smb + (nch & (NSTAGE - 1)) * STG_BYTES;
            size_t bo = (size_t)nch * BK * bstride;
#pragma unroll
            for (int j = 0; j < 2; j++) CP16(base + dA[j], asrc[j] + nch * BK);
#pragma unroll
            for (int j = 0; j < 4; j++) CP16(base + dB[j], bsrc[j] + bo);
        }
        CP_COMMIT();
    }
}

// ---------------------------------------------------------------------------
// GEMM1: h[slot] = tf32round(gelu(Xr[tok] @ W1r[e] + b1[e]))   (z = expert)
// ---------------------------------------------------------------------------
__global__ __launch_bounds__(NTHR, 1) void gemm1_mma(const float* __restrict__ b1)
{
    int e = blockIdx.z;
    int ne = g_cnt[e];
    int row0 = blockIdx.x * BM;
    if (row0 >= ne) return;
    int n0 = blockIdx.y * BN;

    extern __shared__ float sm[];
    uint32_t smb = smem_u32(sm);
    __shared__ int s_tok[BM];

    int tid = threadIdx.x;
    if (tid < BM) {
        int r = row0 + tid;
        s_tok[tid] = (r < ne) ? g_tok[e * T_ + r] : 0;
    }
    __syncthreads();

    const float* asrc[2];
    const float* bsrc[4];
    const float* wbase = g_W1r + (size_t)e * D_ * H_ + n0;
#pragma unroll
    for (int j = 0; j < 2; j++) {
        int seg = tid + NTHR * j;
        asrc[j] = g_Xr + (size_t)s_tok[seg >> 2] * D_ + (seg & 3) * 4;
    }
#pragma unroll
    for (int j = 0; j < 4; j++) {
        int seg = tid + NTHR * j;
        bsrc[j] = wbase + (size_t)(seg >> 6) * H_ + (seg & 63) * 4;
    }

    float acc[4][8][4];
    gemm_pipe<D_ / BK>(sm, smb, asrc, bsrc, H_, acc);

    const int lane = tid & 31, wid = tid >> 5;
    const int wm = wid & 1, wn = wid >> 1;
    const int t4 = lane & 3, g8 = lane >> 2;
    const float* bb = b1 + (size_t)e * H_ + n0;
#pragma unroll
    for (int mi = 0; mi < 4; mi++) {
        int rl0 = wm * 64 + mi * 16 + g8;
#pragma unroll
        for (int half = 0; half < 2; half++) {
            int r = row0 + rl0 + half * 8;
            if (r >= ne) continue;
            float* orow = g_h + ((size_t)(e * T_ + r)) * H_ + n0;
#pragma unroll
            for (int ni = 0; ni < 8; ni++) {
                int cn = wn * 64 + ni * 8 + t4 * 2;
                float v0 = acc[mi][ni][half * 2]     + bb[cn];
                float v1 = acc[mi][ni][half * 2 + 1] + bb[cn + 1];
                float2 o;
                o.x = __uint_as_float(f2tf32(gelu_tanh(v0)));
                o.y = __uint_as_float(f2tf32(gelu_tanh(v1)));
                *(float2*)(orow + cn) = o;
            }
        }
    }
}

// ---------------------------------------------------------------------------
// GEMM2: out[tok] += w * (h[slot] @ W2r[e] + b2[e])   (z = expert)
// ---------------------------------------------------------------------------
__global__ __launch_bounds__(NTHR, 1) void gemm2_mma(const float* __restrict__ b2,
                                                     float* __restrict__ out)
{
    int e = blockIdx.z;
    int ne = g_cnt[e];
    int row0 = blockIdx.x * BM;
    if (row0 >= ne) return;
    int n0 = blockIdx.y * BN;

    extern __shared__ float sm[];
    uint32_t smb = smem_u32(sm);

    int tid = threadIdx.x;
    const float* asrc[2];
    const float* bsrc[4];
    const float* wbase = g_W2r + (size_t)e * H_ * D_ + n0;
#pragma unroll
    for (int j = 0; j < 2; j++) {
        int seg = tid + NTHR * j;
        // rows >= ne read stale-but-finite scratch; masked in epilogue
        asrc[j] = g_h + ((size_t)(e * T_ + row0 + (seg >> 2))) * H_ + (seg & 3) * 4;
    }
#pragma unroll
    for (int j = 0; j < 4; j++) {
        int seg = tid + NTHR * j;
        bsrc[j] = wbase + (size_t)(seg >> 6) * D_ + (seg & 63) * 4;
    }

    float acc[4][8][4];
    gemm_pipe<H_ / BK>(sm, smb, asrc, bsrc, D_, acc);

    const int lane = tid & 31, wid = tid >> 5;
    const int wm = wid & 1, wn = wid >> 1;
    const int t4 = lane & 3, g8 = lane >> 2;
    const float* bb = b2 + (size_t)e * D_ + n0;
#pragma unroll
    for (int mi = 0; mi < 4; mi++) {
        int rl0 = wm * 64 + mi * 16 + g8;
#pragma unroll
        for (int half = 0; half < 2; half++) {
            int r = row0 + rl0 + half * 8;
            if (r >= ne) continue;
            int tok = g_tok[e * T_ + r];
            float wgt = g_wt[e * T_ + r];
            float* orow = out + (size_t)tok * D_ + n0;
#pragma unroll
            for (int ni = 0; ni < 8; ni++) {
                int cn = wn * 64 + ni * 8 + t4 * 2;
                atomicAdd(orow + cn,     wgt * (acc[mi][ni][half * 2]     + bb[cn]));
                atomicAdd(orow + cn + 1, wgt * (acc[mi][ni][half * 2 + 1] + bb[cn + 1]));
            }
        }
    }
}

// ---------------------------------------------------------------------------
extern "C" void kernel_launch(void* const* d_in, const int* in_sizes, int n_in,
                              void* d_out, int out_size)
{
    const float* x  = (const float*)d_in[0];
    const float* Wg = (const float*)d_in[1];
    const float* bg = (const float*)d_in[2];
    const float* W1 = (const float*)d_in[3];
    const float* b1 = (const float*)d_in[4];
    const float* W2 = (const float*)d_in[5];
    const float* b2 = (const float*)d_in[6];
    float* out = (float*)d_out;

    static int inited = 0;
    static cudaStream_t sW;
    static cudaEvent_t ev_root, ev_w1, ev_w2;
    if (!inited) {
        cudaFuncSetAttribute(gemm1_mma, cudaFuncAttributeMaxDynamicSharedMemorySize, SMEM_BYTES);
        cudaFuncSetAttribute(gemm2_mma, cudaFuncAttributeMaxDynamicSharedMemorySize, SMEM_BYTES);
        cudaStreamCreateWithFlags(&sW, cudaStreamNonBlocking);
        cudaEventCreateWithFlags(&ev_root, cudaEventDisableTiming);
        cudaEventCreateWithFlags(&ev_w1,   cudaEventDisableTiming);
        cudaEventCreateWithFlags(&ev_w2,   cudaEventDisableTiming);
        inited = 1;
    }

    float* w1r; cudaGetSymbolAddress((void**)&w1r, g_W1r);
    float* w2r; cudaGetSymbolAddress((void**)&w2r, g_W2r);

    // Fork side stream for weight rounding
    cudaEventRecord(ev_root, 0);
    cudaStreamWaitEvent(sW, ev_root, 0);
    rnd_kernel<<<(E_ * D_ * H_) / 1024, 256, 0, sW>>>(W1, w1r);
    cudaEventRecord(ev_w1, sW);
    rnd_kernel<<<(E_ * H_ * D_) / 1024, 256, 0, sW>>>(W2, w2r);
    cudaEventRecord(ev_w2, sW);

    // Main stream: zero + gate (routing + fused X round) overlap rnd_W1
    zero_kernel<<<(T_ * D_) / (256 * 4), 256>>>(out);
    gate_kernel<<<T_, 256>>>(x, Wg, bg, out);

    // Monolithic GEMMs (z = expert); rnd_W2 overlaps gemm1
    cudaStreamWaitEvent(0, ev_w1, 0);
    gemm1_mma<<<dim3(T_ / BM, H_ / BN, E_), NTHR, SMEM_BYTES>>>(b1);
    cudaStreamWaitEvent(0, ev_w2, 0);
    gemm2_mma<<<dim3(T_ / BM, D_ / BN, E_), NTHR, SMEM_BYTES>>>(b2, out);
}